// round 16
// baseline (speedup 1.0000x reference)
#include <cuda_runtime.h>
#include <math.h>

#define HID 96
#define HC  576
#define NH  6

typedef unsigned long long ull;

__device__ __forceinline__ unsigned f2tf32(float f) {
    unsigned r;
    asm("cvt.rna.tf32.f32 %0, %1;" : "=r"(r) : "f"(f));
    return r;
}
__device__ __forceinline__ ull pack_tf32(float a, float b) {
    unsigned lo = f2tf32(a), hi = f2tf32(b);
    ull r;
    asm("mov.b64 %0, {%1, %2};" : "=l"(r) : "r"(lo), "r"(hi));
    return r;
}
__device__ __forceinline__ void mma_tf32(float c[4],
    unsigned a0, unsigned a1, unsigned a2, unsigned a3,
    unsigned b0, unsigned b1)
{
    asm("mma.sync.aligned.m16n8k8.row.col.f32.tf32.tf32.f32 "
        "{%0,%1,%2,%3},{%4,%5,%6,%7},{%8,%9},{%0,%1,%2,%3};"
        : "+f"(c[0]), "+f"(c[1]), "+f"(c[2]), "+f"(c[3])
        : "r"(a0), "r"(a1), "r"(a2), "r"(a3), "r"(b0), "r"(b1));
}
__device__ __forceinline__ void red_add_v4(float* p, float4 v) {
    asm volatile("red.global.add.v4.f32 [%0], {%1, %2, %3, %4};"
                 :: "l"(p), "f"(v.x), "f"(v.y), "f"(v.z), "f"(v.w) : "memory");
}

// ---------------- scratch ----------------
__device__ float    g_x[20000 * HID];
__device__ float    g_eperm[200000 * HID];
__device__ float    g_xl[20000 * HC];
__device__ float    g_xr[20000 * HC];
__device__ float    g_logits[200000 * NH];
__device__ float    g_den[20000 * NH];
__device__ float    g_hmean[20000 * HID];
__device__ int      g_cnt[20000];
__device__ int      g_cur[20000];
__device__ int      g_basep[20000];
__device__ int      g_perm[200000];
__device__ int      g_psrc[200000];
__device__ int      g_pdst[200000];

__device__ __forceinline__ float warpsum32(float v) {
#pragma unroll
    for (int m = 16; m; m >>= 1) v += __shfl_xor_sync(0xffffffffu, v, m);
    return v;
}

// ---------------- sort-by-dst kernels ----------------
__global__ void hist_kernel(const int* __restrict__ dst, int* __restrict__ cnt, int E) {
    int e = blockIdx.x * blockDim.x + threadIdx.x;
    if (e < E) atomicAdd(&cnt[dst[e]], 1);
}
__global__ void scan_kernel(const int* __restrict__ cnt, int* __restrict__ base, int Nn) {
    __shared__ int wsum[32];
    int t = threadIdx.x;
    int lane = t & 31, w = t >> 5;
    int start = t * 20;
    int s = 0;
    int loc[20];
#pragma unroll
    for (int i = 0; i < 20; i++) {
        int idx = start + i;
        int v = (idx < Nn) ? cnt[idx] : 0;
        loc[i] = v; s += v;
    }
    int inc = s;
#pragma unroll
    for (int off = 1; off < 32; off <<= 1) {
        int v = __shfl_up_sync(0xffffffffu, inc, off);
        if (lane >= off) inc += v;
    }
    if (lane == 31) wsum[w] = inc;
    __syncthreads();
    if (w == 0) {
        int v = (lane < 32) ? wsum[lane] : 0;
        int wi = v;
#pragma unroll
        for (int off = 1; off < 32; off <<= 1) {
            int u = __shfl_up_sync(0xffffffffu, wi, off);
            if (lane >= off) wi += u;
        }
        wsum[lane] = wi - v;
    }
    __syncthreads();
    int run = wsum[w] + inc - s;
#pragma unroll
    for (int i = 0; i < 20; i++) {
        int idx = start + i;
        if (idx < Nn) { base[idx] = run; run += loc[i]; }
    }
}
__global__ void scatter_kernel(const int* __restrict__ src, const int* __restrict__ dst,
                               const int* __restrict__ base, int* __restrict__ cur,
                               int* __restrict__ perm, int* __restrict__ psrc,
                               int* __restrict__ pdst, int E)
{
    int e = blockIdx.x * blockDim.x + threadIdx.x;
    if (e >= E) return;
    int d = dst[e];
    int pos = base[d] + atomicAdd(&cur[d], 1);
    perm[pos] = e;
    psrc[pos] = src[e];
    pdst[pos] = d;
}

// ---------------- encoder (optional row-gather via perm) ----------------
__global__ void encoder_kernel(const float* __restrict__ in, int Fin,
                               const float* __restrict__ W, const float* __restrict__ b,
                               const float* __restrict__ g, const float* __restrict__ beta,
                               float* __restrict__ out, int M,
                               const int* __restrict__ perm)
{
    int w    = (blockIdx.x * blockDim.x + threadIdx.x) >> 5;
    int lane = threadIdx.x & 31;
    if (w >= M) return;
    int row = perm ? perm[w] : w;
    float xin[4];
#pragma unroll
    for (int k = 0; k < 4; k++) xin[k] = (k < Fin) ? in[(size_t)row * Fin + k] : 0.f;
    float v[3];
#pragma unroll
    for (int j = 0; j < 3; j++) {
        int c = lane + 32 * j;
        float acc = b[c];
        for (int k = 0; k < Fin; k++) acc = fmaf(xin[k], W[k * HID + c], acc);
        v[j] = acc;
    }
    float mu = warpsum32(v[0] + v[1] + v[2]) * (1.f / 96.f);
    float q = 0.f;
#pragma unroll
    for (int j = 0; j < 3; j++) { float d = v[j] - mu; q = fmaf(d, d, q); }
    float rstd = rsqrtf(warpsum32(q) * (1.f / 96.f) + 1e-5f);
#pragma unroll
    for (int j = 0; j < 3; j++) {
        int c = lane + 32 * j;
        float y = (v[j] - mu) * rstd * g[c] + beta[c];
        out[(size_t)w * HID + c] = fmaxf(y, 0.f);
    }
}

// ---------------- dual node tf32 GEMM ----------------
#define AU_ULL (12 * 512)
#define BU_ULL (12 * 384)
#define TFD_SMEM ((AU_ULL + 2 * BU_ULL) * 8)

__global__ __launch_bounds__(384) void tf32_dual_gemm_kernel(
    const float* __restrict__ Ag,
    const float* __restrict__ Bl, const float* __restrict__ Br,
    const float* __restrict__ bl, const float* __restrict__ br,
    float* __restrict__ Cl, float* __restrict__ Cr, int M)
{
    extern __shared__ ull sh64[];
    ull* Au  = sh64;
    ull* BuL = sh64 + AU_ULL;
    ull* BuR = BuL + BU_ULL;

    int tid = threadIdx.x;
    int m0 = blockIdx.x * 128, n0 = blockIdx.y * 96;

    {
        int row = tid & 127;
        int kg  = tid >> 7;
        int m = m0 + row;
        const float* arow = Ag + (size_t)m * 96;
#pragma unroll
        for (int i = 0; i < 4; i++) {
            int ks = kg * 4 + i;
            float4 lo = make_float4(0.f, 0.f, 0.f, 0.f);
            float4 hi = make_float4(0.f, 0.f, 0.f, 0.f);
            if (m < M) {
                lo = *(const float4*)(arow + ks * 8);
                hi = *(const float4*)(arow + ks * 8 + 4);
            }
            ull* dstp = Au + ks * 512 + row * 4;
            *(ulonglong2*)(dstp)     = make_ulonglong2(pack_tf32(lo.x, hi.x), pack_tf32(lo.y, hi.y));
            *(ulonglong2*)(dstp + 2) = make_ulonglong2(pack_tf32(lo.z, hi.z), pack_tf32(lo.w, hi.w));
        }
    }
    for (int t = tid; t < 2304; t += 384) {
        int side = t >= 1152;
        int tt = t - side * 1152;
        int ks  = tt / 96;
        int rem = tt - ks * 96;
        int q = rem >> 2, r = rem & 3;
        const float* Bg = side ? Br : Bl;
        const float* b0 = Bg + (size_t)(ks * 8 + r) * HC + n0 + q * 4;
        float4 lo = *(const float4*)b0;
        float4 hi = *(const float4*)(b0 + 4 * HC);
        ull* dstb = (side ? BuR : BuL) + ks * 384 + q * 16 + r;
        dstb[0]  = pack_tf32(lo.x, hi.x);
        dstb[4]  = pack_tf32(lo.y, hi.y);
        dstb[8]  = pack_tf32(lo.z, hi.z);
        dstb[12] = pack_tf32(lo.w, hi.w);
    }
    __syncthreads();

    int wid = tid >> 5, lane = tid & 31;
    int wm = wid & 3, wn = wid >> 2;
    int g = lane >> 2, tig = lane & 3;
    int rowb = wm * 32, colb = wn * 32;

#pragma unroll
    for (int side = 0; side < 2; side++) {
        const ull* Bu = side ? BuR : BuL;
        const float* bias = side ? br : bl;
        float* C = side ? Cr : Cl;

        float acc[2][4][4];
#pragma unroll
        for (int mt = 0; mt < 2; mt++)
#pragma unroll
            for (int nt = 0; nt < 4; nt++)
#pragma unroll
                for (int q = 0; q < 4; q++) acc[mt][nt][q] = 0.f;

#pragma unroll
        for (int ks = 0; ks < 12; ks++) {
            const ull* Ak = Au + ks * 512;
            const ull* Bk = Bu + ks * 384;
            uint2 pa[2][2];
#pragma unroll
            for (int mt = 0; mt < 2; mt++) {
                int rb = rowb + mt * 16 + g;
                pa[mt][0] = *(const uint2*)(Ak + rb * 4 + tig);
                pa[mt][1] = *(const uint2*)(Ak + (rb + 8) * 4 + tig);
            }
#pragma unroll
            for (int nt = 0; nt < 4; nt++) {
                int cb = colb + nt * 8 + g;
                uint2 pb = *(const uint2*)(Bk + cb * 4 + tig);
#pragma unroll
                for (int mt = 0; mt < 2; mt++)
                    mma_tf32(acc[mt][nt],
                             pa[mt][0].x, pa[mt][1].x, pa[mt][0].y, pa[mt][1].y,
                             pb.x, pb.y);
            }
        }

#pragma unroll
        for (int nt = 0; nt < 4; nt++) {
            int c = n0 + colb + nt * 8 + 2 * tig;
            float2 bq = *(const float2*)(bias + c);
#pragma unroll
            for (int mt = 0; mt < 2; mt++) {
                int r0 = m0 + rowb + mt * 16 + g;
                if (r0 < M) {
                    float2 o = make_float2(acc[mt][nt][0] + bq.x, acc[mt][nt][1] + bq.y);
                    *(float2*)(C + (size_t)r0 * HC + c) = o;
                }
                int r1 = r0 + 8;
                if (r1 < M) {
                    float2 o = make_float2(acc[mt][nt][2] + bq.x, acc[mt][nt][3] + bq.y);
                    *(float2*)(C + (size_t)r1 * HC + c) = o;
                }
            }
        }
    }
}

// ---------------- fused edge kernel: heads processed in PAIRS ----------------
// A fragments loaded once per ks and shared by both heads of the pair.
#define EAU (12 * 512)
#define EBU (12 * 384)
#define EDGE_SMEM ((EAU + 2 * EBU) * 8 + 128 * 8 * 4 + 128 * 2 * 4)

__global__ __launch_bounds__(384) void edge_fused_kernel(
    const float* __restrict__ Ag, const float* __restrict__ Bg, int M,
    const int* __restrict__ src, const int* __restrict__ dst,
    const float* __restrict__ xl, const float* __restrict__ xr,
    const float* __restrict__ attw, float* __restrict__ logits,
    float* __restrict__ den)
{
    extern __shared__ ull sh64[];
    ull* Au  = sh64;
    ull* Bu0 = sh64 + EAU;
    ull* Bu1 = Bu0 + EBU;
    float* s_logit = (float*)(Bu1 + EBU);
    int*   s_src   = (int*)(s_logit + 128 * 8);
    int*   s_dst   = s_src + 128;

    int tid = threadIdx.x;
    int m0 = blockIdx.x * 128;

    for (int i = tid; i < 128 * 8; i += 384) s_logit[i] = 0.f;
    if (tid < 128) {
        int e = m0 + tid;
        int ec = (e < M) ? e : (M - 1);
        s_src[tid] = src[ec];
        s_dst[tid] = dst[ec];
    }

    // stage A once
    {
        int row = tid & 127;
        int kg  = tid >> 7;
        int m = m0 + row;
        const float* arow = Ag + (size_t)m * 96;
#pragma unroll
        for (int i = 0; i < 4; i++) {
            int ks = kg * 4 + i;
            float4 lo = make_float4(0.f, 0.f, 0.f, 0.f);
            float4 hi = make_float4(0.f, 0.f, 0.f, 0.f);
            if (m < M) {
                lo = *(const float4*)(arow + ks * 8);
                hi = *(const float4*)(arow + ks * 8 + 4);
            }
            ull* dstp = Au + ks * 512 + row * 4;
            *(ulonglong2*)(dstp)     = make_ulonglong2(pack_tf32(lo.x, hi.x), pack_tf32(lo.y, hi.y));
            *(ulonglong2*)(dstp + 2) = make_ulonglong2(pack_tf32(lo.z, hi.z), pack_tf32(lo.w, hi.w));
        }
    }
    // stage B for heads 0 and 1
    for (int t = tid; t < 2304; t += 384) {
        int hh = t >= 1152;
        int tt = t - hh * 1152;
        int ks  = tt / 96;
        int rem = tt - ks * 96;
        int q = rem >> 2, r = rem & 3;
        const float* b0 = Bg + (size_t)(ks * 8 + r) * HC + hh * 96 + q * 4;
        float4 lo = *(const float4*)b0;
        float4 hi = *(const float4*)(b0 + 4 * HC);
        ull* dstb = (hh ? Bu1 : Bu0) + ks * 384 + q * 16 + r;
        dstb[0]  = pack_tf32(lo.x, hi.x);
        dstb[4]  = pack_tf32(lo.y, hi.y);
        dstb[8]  = pack_tf32(lo.z, hi.z);
        dstb[12] = pack_tf32(lo.w, hi.w);
    }
    __syncthreads();

    int wid = tid >> 5, lane = tid & 31;
    int wm = wid & 3, wn = wid >> 2;
    int g = lane >> 2, tig = lane & 3;
    int rowb = wm * 32, colb = wn * 32;

    for (int hp = 0; hp < 3; hp++) {
        // prefetch next pair's B into registers
        float4 plo[6], phi[6];
        if (hp < 2) {
#pragma unroll
            for (int pp = 0; pp < 6; pp++) {
                int hh = pp >= 3;
                int it = pp - hh * 3;
                int t = tid + 384 * it;
                int ks  = t / 96;
                int rem = t - ks * 96;
                int q = rem >> 2, r = rem & 3;
                const float* b0 = Bg + (size_t)(ks * 8 + r) * HC + (2 * hp + 2 + hh) * 96 + q * 4;
                plo[pp] = *(const float4*)b0;
                phi[pp] = *(const float4*)(b0 + 4 * HC);
            }
        }

        float acc[2][2][4][4];
#pragma unroll
        for (int hh = 0; hh < 2; hh++)
#pragma unroll
            for (int mt = 0; mt < 2; mt++)
#pragma unroll
                for (int nt = 0; nt < 4; nt++)
#pragma unroll
                    for (int q = 0; q < 4; q++) acc[hh][mt][nt][q] = 0.f;

#pragma unroll
        for (int ks = 0; ks < 12; ks++) {
            const ull* Ak  = Au + ks * 512;
            const ull* Bk0 = Bu0 + ks * 384;
            const ull* Bk1 = Bu1 + ks * 384;
            uint2 pa[2][2];
#pragma unroll
            for (int mt = 0; mt < 2; mt++) {
                int rb = rowb + mt * 16 + g;
                pa[mt][0] = *(const uint2*)(Ak + rb * 4 + tig);
                pa[mt][1] = *(const uint2*)(Ak + (rb + 8) * 4 + tig);
            }
#pragma unroll
            for (int nt = 0; nt < 4; nt++) {
                int cb = colb + nt * 8 + g;
                uint2 pb0 = *(const uint2*)(Bk0 + cb * 4 + tig);
                uint2 pb1 = *(const uint2*)(Bk1 + cb * 4 + tig);
#pragma unroll
                for (int mt = 0; mt < 2; mt++) {
                    mma_tf32(acc[0][mt][nt],
                             pa[mt][0].x, pa[mt][1].x, pa[mt][0].y, pa[mt][1].y,
                             pb0.x, pb0.y);
                    mma_tf32(acc[1][mt][nt],
                             pa[mt][0].x, pa[mt][1].x, pa[mt][0].y, pa[mt][1].y,
                             pb1.x, pb1.y);
                }
            }
        }

        // epilogue for both heads of the pair
#pragma unroll
        for (int hh = 0; hh < 2; hh++) {
            int h = 2 * hp + hh;
#pragma unroll
            for (int mt = 0; mt < 2; mt++) {
#pragma unroll
                for (int half = 0; half < 2; half++) {
                    int ml = rowb + mt * 16 + half * 8 + g;
                    int m = m0 + ml;
                    float partial = 0.f;
                    if (m < M) {
                        int s = s_src[ml], d = s_dst[ml];
                        const float* xls = xl + (size_t)s * HC;
                        const float* xrd = xr + (size_t)d * HC;
#pragma unroll
                        for (int nt = 0; nt < 4; nt++) {
                            int c = h * 96 + colb + nt * 8 + 2 * tig;
                            float2 xlv = *(const float2*)(xls + c);
                            float2 xrv = *(const float2*)(xrd + c);
                            float aw0 = attw[c], aw1 = attw[c + 1];
                            float a0 = acc[hh][mt][nt][half * 2 + 0];
                            float a1 = acc[hh][mt][nt][half * 2 + 1];
                            float t0 = a0 + xlv.x + xrv.x; t0 = (t0 > 0.f) ? t0 : 0.2f * t0;
                            float t1 = a1 + xlv.y + xrv.y; t1 = (t1 > 0.f) ? t1 : 0.2f * t1;
                            partial = fmaf(t0, aw0, fmaf(t1, aw1, partial));
                        }
                    }
                    partial += __shfl_down_sync(0xffffffffu, partial, 1, 4);
                    partial += __shfl_down_sync(0xffffffffu, partial, 2, 4);
                    if (tig == 0 && m < M)
                        atomicAdd(&s_logit[ml * 8 + h], partial);
                }
            }
        }

        if (hp < 2) {
            __syncthreads();          // all warps done reading Bu0/Bu1
#pragma unroll
            for (int pp = 0; pp < 6; pp++) {
                int hh = pp >= 3;
                int it = pp - hh * 3;
                int t = tid + 384 * it;
                int ks  = t / 96;
                int rem = t - ks * 96;
                int q = rem >> 2, r = rem & 3;
                ull* dstb = (hh ? Bu1 : Bu0) + ks * 384 + q * 16 + r;
                dstb[0]  = pack_tf32(plo[pp].x, phi[pp].x);
                dstb[4]  = pack_tf32(plo[pp].y, phi[pp].y);
                dstb[8]  = pack_tf32(plo[pp].z, phi[pp].z);
                dstb[12] = pack_tf32(plo[pp].w, phi[pp].w);
            }
            __syncthreads();
        }
    }
    __syncthreads();

    for (int t = tid; t < 128 * NH; t += 384) {
        int el = t / NH, h = t - el * NH;
        int e = m0 + el;
        if (e < M) {
            float ex = expf(s_logit[el * 8 + h]);
            logits[(size_t)e * NH + h] = ex;
            atomicAdd(&den[s_dst[el] * NH + h], ex);
        }
    }
}

// ---------------- aggregate (red.v4) ----------------
__global__ void agg_kernel(const int* __restrict__ src, const int* __restrict__ dst,
                           const float* __restrict__ ex, const float* __restrict__ den,
                           const float* __restrict__ xl, float* __restrict__ hmean, int E)
{
    int e    = (blockIdx.x * blockDim.x + threadIdx.x) >> 5;
    int lane = threadIdx.x & 31;
    if (e >= E) return;
    int s = src[e], d = dst[e];
    float a = 0.f;
    if (lane < NH) a = ex[e * NH + lane] / (den[d * NH + lane] + 1e-16f);
    float alpha[NH];
#pragma unroll
    for (int h = 0; h < NH; h++) alpha[h] = __shfl_sync(0xffffffffu, a, h) * (1.f / 6.f);
    if (lane < 24) {
        const float* xls = xl + (size_t)s * HC + lane * 4;
        float4 v = make_float4(0.f, 0.f, 0.f, 0.f);
#pragma unroll
        for (int h = 0; h < NH; h++) {
            float4 xv = *(const float4*)(xls + h * 96);
            v.x = fmaf(alpha[h], xv.x, v.x);
            v.y = fmaf(alpha[h], xv.y, v.y);
            v.z = fmaf(alpha[h], xv.z, v.z);
            v.w = fmaf(alpha[h], xv.w, v.w);
        }
        red_add_v4(hmean + (size_t)d * HID + lane * 4, v);
    }
}

// ---------------- node update ----------------
__global__ void nodeupd_kernel(const float* __restrict__ cb, const float* __restrict__ g,
                               const float* __restrict__ bt, int doElu,
                               const float* __restrict__ hmean, float* __restrict__ x, int M)
{
    int n    = (blockIdx.x * blockDim.x + threadIdx.x) >> 5;
    int lane = threadIdx.x & 31;
    if (n >= M) return;
    float v[3];
#pragma unroll
    for (int j = 0; j < 3; j++) {
        int c = lane + 32 * j;
        float hv = hmean[(size_t)n * HID + c] + cb[c];
        if (doElu) hv = (hv > 0.f) ? hv : (expf(hv) - 1.f);
        v[j] = hv;
    }
    float mu = warpsum32(v[0] + v[1] + v[2]) * (1.f / 96.f);
    float q = 0.f;
#pragma unroll
    for (int j = 0; j < 3; j++) { float d = v[j] - mu; q = fmaf(d, d, q); }
    float rstd = rsqrtf(warpsum32(q) * (1.f / 96.f) + 1e-5f);
#pragma unroll
    for (int j = 0; j < 3; j++) {
        int c = lane + 32 * j;
        float y = (v[j] - mu) * rstd * g[c] + bt[c];
        x[(size_t)n * HID + c] += y;
    }
}

// ---------------- tf32 predictor (permuted space; scatters output) ---------
#define PAU (16 * 512)
#define PBU (12 * 512)
#define PH1 (128 * 132)
#define PCN (384 + 192 + 64)
#define PRED_SMEM ((PAU + PBU) * 8 + PH1 * 4 + (PCN + 256) * 4)

__global__ __launch_bounds__(256) void predictor_kernel(
    const int* __restrict__ src, const int* __restrict__ dst,
    const int* __restrict__ perm,
    const float* __restrict__ xnode, const float* __restrict__ eemb,
    const float* __restrict__ p1w, const float* __restrict__ p1b,
    const float* __restrict__ p1g, const float* __restrict__ p1bt,
    const float* __restrict__ p2w, const float* __restrict__ p2b,
    const float* __restrict__ p2g, const float* __restrict__ p2bt,
    const float* __restrict__ p3w, const float* __restrict__ p3b,
    float* __restrict__ out, int E)
{
    extern __shared__ ull sh64[];
    ull*   Au   = sh64;
    ull*   Bu   = sh64 + PAU;
    float* s_h1 = (float*)(Bu + PBU);
    float* s_c1 = s_h1 + PH1;
    float* s_c2 = s_c1 + 384;
    float* s_p3 = s_c2 + 192;
    int*   s_ed = (int*)(s_p3 + 64);

    int tid = threadIdx.x;
    int m0 = blockIdx.x * 128;

    if (tid < 128) {
        s_c1[tid] = p1b[tid]; s_c1[128 + tid] = p1g[tid]; s_c1[256 + tid] = p1bt[tid];
        int e = m0 + tid; int ec = (e < E) ? e : (E - 1);
        s_ed[tid] = src[ec]; s_ed[128 + tid] = dst[ec];
    }
    if (tid < 64) {
        s_c2[tid] = p2b[tid]; s_c2[64 + tid] = p2g[tid]; s_c2[128 + tid] = p2bt[tid];
        s_p3[tid] = p3w[tid];
    }
    __syncthreads();

    int wid = tid >> 5, lane = tid & 31;
    int wm = wid & 3, wn = wid >> 2;
    int g = lane >> 2, tig = lane & 3;
    int rowb = wm * 32, colb = wn * 64;

    float acc1[2][8][4];
#pragma unroll
    for (int mt = 0; mt < 2; mt++)
#pragma unroll
        for (int nt = 0; nt < 8; nt++)
#pragma unroll
            for (int q = 0; q < 4; q++) acc1[mt][nt][q] = 0.f;

    for (int c = 0; c < 3; c++) {
        {
            int row = tid & 127;
            int kg  = tid >> 7;
            const float* arow;
            if (c == 0)      arow = xnode + (size_t)s_ed[row] * HID;
            else if (c == 1) arow = xnode + (size_t)s_ed[128 + row] * HID;
            else {
                int e = m0 + row; int ec = (e < E) ? e : (E - 1);
                arow = eemb + (size_t)ec * HID;
            }
#pragma unroll
            for (int i = 0; i < 6; i++) {
                int ks = kg * 6 + i;
                float4 lo = *(const float4*)(arow + ks * 8);
                float4 hi = *(const float4*)(arow + ks * 8 + 4);
                ull* dstp = Au + ks * 512 + row * 4;
                *(ulonglong2*)(dstp)     = make_ulonglong2(pack_tf32(lo.x, hi.x), pack_tf32(lo.y, hi.y));
                *(ulonglong2*)(dstp + 2) = make_ulonglong2(pack_tf32(lo.z, hi.z), pack_tf32(lo.w, hi.w));
            }
        }
#pragma unroll
        for (int it = 0; it < 24; it++) {
            int t = tid + 256 * it;
            int ks = t >> 9, rem = t & 511;
            int col = rem >> 2, r = rem & 3;
            int k0 = c * 96 + ks * 8 + r;
            Bu[ks * 512 + col * 4 + r] =
                pack_tf32(p1w[(size_t)k0 * 128 + col], p1w[(size_t)(k0 + 4) * 128 + col]);
        }
        __syncthreads();

#pragma unroll
        for (int ks = 0; ks < 12; ks++) {
            const ull* Ak = Au + ks * 512;
            const ull* Bk = Bu + ks * 512;
            uint2 pa[2][2];
#pragma unroll
            for (int mt = 0; mt < 2; mt++) {
                int rb = rowb + mt * 16 + g;
                pa[mt][0] = *(const uint2*)(Ak + rb * 4 + tig);
                pa[mt][1] = *(const uint2*)(Ak + (rb + 8) * 4 + tig);
            }
#pragma unroll
            for (int nt = 0; nt < 8; nt++) {
                int cb = colb + nt * 8 + g;
                uint2 pb = *(const uint2*)(Bk + cb * 4 + tig);
#pragma unroll
                for (int mt = 0; mt < 2; mt++)
                    mma_tf32(acc1[mt][nt],
                             pa[mt][0].x, pa[mt][1].x, pa[mt][0].y, pa[mt][1].y,
                             pb.x, pb.y);
            }
        }
        __syncthreads();
    }

#pragma unroll
    for (int nt = 0; nt < 8; nt++) {
        int col = colb + nt * 8 + 2 * tig;
        float b0 = s_c1[col], b1 = s_c1[col + 1];
#pragma unroll
        for (int mt = 0; mt < 2; mt++) {
            int r0 = rowb + mt * 16 + g;
            s_h1[r0 * 132 + col]     = acc1[mt][nt][0] + b0;
            s_h1[r0 * 132 + col + 1] = acc1[mt][nt][1] + b1;
            int r1 = r0 + 8;
            s_h1[r1 * 132 + col]     = acc1[mt][nt][2] + b0;
            s_h1[r1 * 132 + col + 1] = acc1[mt][nt][3] + b1;
        }
    }
    __syncthreads();

    for (int rr = 0; rr < 16; rr++) {
        int row = wid * 16 + rr;
        float4 v = ((float4*)(s_h1 + row * 132))[lane];
        float mu = warpsum32(v.x + v.y + v.z + v.w) * (1.f / 128.f);
        float q = 0.f, d;
        d = v.x - mu; q = fmaf(d, d, q);
        d = v.y - mu; q = fmaf(d, d, q);
        d = v.z - mu; q = fmaf(d, d, q);
        d = v.w - mu; q = fmaf(d, d, q);
        float r = rsqrtf(warpsum32(q) * (1.f / 128.f) + 1e-5f);
        int c0 = lane * 4;
        float4 gm = *(float4*)(s_c1 + 128 + c0);
        float4 bt = *(float4*)(s_c1 + 256 + c0);
        v.x = fmaxf((v.x - mu) * r * gm.x + bt.x, 0.f);
        v.y = fmaxf((v.y - mu) * r * gm.y + bt.y, 0.f);
        v.z = fmaxf((v.z - mu) * r * gm.z + bt.z, 0.f);
        v.w = fmaxf((v.w - mu) * r * gm.w + bt.w, 0.f);
        ((float4*)(s_h1 + row * 132))[lane] = v;
    }
    __syncthreads();

    {
        int row = tid & 127;
        int kg  = tid >> 7;
        const float* hrow = s_h1 + row * 132;
#pragma unroll
        for (int i = 0; i < 8; i++) {
            int ks = kg * 8 + i;
            float4 lo = *(const float4*)(hrow + ks * 8);
            float4 hi = *(const float4*)(hrow + ks * 8 + 4);
            ull* dstp = Au + ks * 512 + row * 4;
            *(ulonglong2*)(dstp)     = make_ulonglong2(pack_tf32(lo.x, hi.x), pack_tf32(lo.y, hi.y));
            *(ulonglong2*)(dstp + 2) = make_ulonglong2(pack_tf32(lo.z, hi.z), pack_tf32(lo.w, hi.w));
        }
    }
#pragma unroll
    for (int it = 0; it < 16; it++) {
        int t = tid + 256 * it;
        int ks = t >> 8, rem = t & 255;
        int col = rem >> 2, r = rem & 3;
        int k0 = ks * 8 + r;
        Bu[ks * 256 + col * 4 + r] =
            pack_tf32(p2w[(size_t)k0 * 64 + col], p2w[(size_t)(k0 + 4) * 64 + col]);
    }
    __syncthreads();

    int colb2 = wn * 32;
    float acc2[2][4][4];
#pragma unroll
    for (int mt = 0; mt < 2; mt++)
#pragma unroll
        for (int nt = 0; nt < 4; nt++)
#pragma unroll
            for (int q = 0; q < 4; q++) acc2[mt][nt][q] = 0.f;

#pragma unroll
    for (int ks = 0; ks < 16; ks++) {
        const ull* Ak = Au + ks * 512;
        const ull* Bk = Bu + ks * 256;
        uint2 pa[2][2];
#pragma unroll
        for (int mt = 0; mt < 2; mt++) {
            int rb = rowb + mt * 16 + g;
            pa[mt][0] = *(const uint2*)(Ak + rb * 4 + tig);
            pa[mt][1] = *(const uint2*)(Ak + (rb + 8) * 4 + tig);
        }
#pragma unroll
        for (int nt = 0; nt < 4; nt++) {
            int cb = colb2 + nt * 8 + g;
            uint2 pb = *(const uint2*)(Bk + cb * 4 + tig);
#pragma unroll
            for (int mt = 0; mt < 2; mt++)
                mma_tf32(acc2[mt][nt],
                         pa[mt][0].x, pa[mt][1].x, pa[mt][0].y, pa[mt][1].y,
                         pb.x, pb.y);
        }
    }
    __syncthreads();

#pragma unroll
    for (int nt = 0; nt < 4; nt++) {
        int col = colb2 + nt * 8 + 2 * tig;
        float b0 = s_c2[col], b1 = s_c2[col + 1];
#pragma unroll
        for (int mt = 0; mt < 2; mt++) {
            int r0 = rowb + mt * 16 + g;
            s_h1[r0 * 68 + col]     = acc2[mt][nt][0] + b0;
            s_h1[r0 * 68 + col + 1] = acc2[mt][nt][1] + b1;
            int r1 = r0 + 8;
            s_h1[r1 * 68 + col]     = acc2[mt][nt][2] + b0;
            s_h1[r1 * 68 + col + 1] = acc2[mt][nt][3] + b1;
        }
    }
    __syncthreads();

    float pb = p3b[0];
    for (int rr = 0; rr < 16; rr++) {
        int row = wid * 16 + rr;
        float2 v = ((float2*)(s_h1 + row * 68))[lane];
        float mu = warpsum32(v.x + v.y) * (1.f / 64.f);
        float q = 0.f, d;
        d = v.x - mu; q = fmaf(d, d, q);
        d = v.y - mu; q = fmaf(d, d, q);
        float r = rsqrtf(warpsum32(q) * (1.f / 64.f) + 1e-5f);
        int c0 = lane * 2;
        float gm0 = s_c2[64 + c0], gm1 = s_c2[64 + c0 + 1];
        float bt0 = s_c2[128 + c0], bt1 = s_c2[128 + c0 + 1];
        float v0 = fmaxf((v.x - mu) * r * gm0 + bt0, 0.f);
        float v1 = fmaxf((v.y - mu) * r * gm1 + bt1, 0.f);
        float o = warpsum32(v0 * s_p3[c0] + v1 * s_p3[c0 + 1]);
        if (lane == 0) {
            int e = m0 + row;
            if (e < E) out[perm[e]] = o + pb;
        }
    }
}

// ---------------- launch ----------------
extern "C" void kernel_launch(void* const* d_in, const int* in_sizes, int n_in,
                              void* d_out, int out_size)
{
    const float* x         = (const float*)d_in[0];
    const float* edge_attr = (const float*)d_in[1];
    const int*   edge_idx  = (const int*)d_in[2];
    const float* ne_w = (const float*)d_in[3];
    const float* ne_b = (const float*)d_in[4];
    const float* ne_g = (const float*)d_in[5];
    const float* ne_bt = (const float*)d_in[6];
    const float* ee_w = (const float*)d_in[7];
    const float* ee_b = (const float*)d_in[8];
    const float* ee_g = (const float*)d_in[9];
    const float* ee_bt = (const float*)d_in[10];
    const float* Wl = (const float*)d_in[11];
    const float* bl = (const float*)d_in[12];
    const float* Wr = (const float*)d_in[13];
    const float* br = (const float*)d_in[14];
    const float* We = (const float*)d_in[15];
    const float* attw = (const float*)d_in[16];
    const float* cbias = (const float*)d_in[17];
    const float* lng = (const float*)d_in[18];
    const float* lnb = (const float*)d_in[19];
    const float* p1w = (const float*)d_in[20];
    const float* p1b = (const float*)d_in[21];
    const float* p1g = (const float*)d_in[22];
    const float* p1bt = (const float*)d_in[23];
    const float* p2w = (const float*)d_in[24];
    const float* p2b = (const float*)d_in[25];
    const float* p2g = (const float*)d_in[26];
    const float* p2bt = (const float*)d_in[27];
    const float* p3w = (const float*)d_in[28];
    const float* p3b = (const float*)d_in[29];

    int Nn = in_sizes[0] / 4;
    int E  = in_sizes[1] / 3;
    const int* srcp = edge_idx;
    const int* dstp = edge_idx + E;
    float* outp = (float*)d_out;

    void *px_, *pep_, *pxl_, *pxr_, *plog_, *pden_, *phm_;
    void *pcnt_, *pcur_, *pbase_, *pperm_, *ppsrc_, *ppdst_;
    cudaGetSymbolAddress(&px_, g_x);
    cudaGetSymbolAddress(&pep_, g_eperm);
    cudaGetSymbolAddress(&pxl_, g_xl);
    cudaGetSymbolAddress(&pxr_, g_xr);
    cudaGetSymbolAddress(&plog_, g_logits);
    cudaGetSymbolAddress(&pden_, g_den);
    cudaGetSymbolAddress(&phm_, g_hmean);
    cudaGetSymbolAddress(&pcnt_, g_cnt);
    cudaGetSymbolAddress(&pcur_, g_cur);
    cudaGetSymbolAddress(&pbase_, g_basep);
    cudaGetSymbolAddress(&pperm_, g_perm);
    cudaGetSymbolAddress(&ppsrc_, g_psrc);
    cudaGetSymbolAddress(&ppdst_, g_pdst);
    float* px = (float*)px_;   float* pep = (float*)pep_;
    float* pxl = (float*)pxl_; float* pxr = (float*)pxr_;
    float* plog = (float*)plog_;
    float* pden = (float*)pden_; float* phm = (float*)phm_;
    int* pcnt = (int*)pcnt_; int* pcur = (int*)pcur_; int* pbase = (int*)pbase_;
    int* pperm = (int*)pperm_; int* ppsrc = (int*)ppsrc_; int* ppdst = (int*)ppdst_;

    cudaFuncSetAttribute(tf32_dual_gemm_kernel,
                         cudaFuncAttributeMaxDynamicSharedMemorySize, TFD_SMEM);
    cudaFuncSetAttribute(edge_fused_kernel,
                         cudaFuncAttributeMaxDynamicSharedMemorySize, EDGE_SMEM);
    cudaFuncSetAttribute(predictor_kernel,
                         cudaFuncAttributeMaxDynamicSharedMemorySize, PRED_SMEM);

    // sort first (depends only on edge_index)
    cudaMemsetAsync(pcnt, 0, (size_t)Nn * sizeof(int), 0);
    cudaMemsetAsync(pcur, 0, (size_t)Nn * sizeof(int), 0);
    hist_kernel<<<(E + 255) / 256, 256>>>(dstp, pcnt, E);
    scan_kernel<<<1, 1024>>>(pcnt, pbase, Nn);
    scatter_kernel<<<(E + 255) / 256, 256>>>(srcp, dstp, pbase, pcur,
                                             pperm, ppsrc, ppdst, E);

    // encoders (edge encoder writes directly in permuted order)
    encoder_kernel<<<(Nn + 7) / 8, 256>>>(x, 4, ne_w, ne_b, ne_g, ne_bt, px, Nn,
                                          (const int*)0);
    encoder_kernel<<<(E + 7) / 8, 256>>>(edge_attr, 3, ee_w, ee_b, ee_g, ee_bt, pep, E,
                                         pperm);

    dim3 gNt((Nn + 127) / 128, HC / 96);
    int gEb = (E + 127) / 128;

    for (int l = 0; l < 3; l++) {
        const float* Wl_l = Wl + (size_t)l * 96 * HC;
        const float* Wr_l = Wr + (size_t)l * 96 * HC;
        const float* We_l = We + (size_t)l * 96 * HC;
        tf32_dual_gemm_kernel<<<gNt, 384, TFD_SMEM>>>(px, Wl_l, Wr_l,
                                                      bl + l * HC, br + l * HC,
                                                      pxl, pxr, Nn);

        cudaMemsetAsync(pden, 0, (size_t)Nn * NH * sizeof(float), 0);
        cudaMemsetAsync(phm, 0, (size_t)Nn * HID * sizeof(float), 0);

        edge_fused_kernel<<<gEb, 384, EDGE_SMEM>>>(pep, We_l, E, ppsrc, ppdst,
                                                   pxl, pxr, attw + l * NH * 96,
                                                   plog, pden);

        agg_kernel<<<(E + 7) / 8, 256>>>(ppsrc, ppdst, plog, pden, pxl, phm, E);
        nodeupd_kernel<<<(Nn + 7) / 8, 256>>>(cbias + l * HID, lng + l * HID,
                                              lnb + l * HID, (l < 2) ? 1 : 0, phm, px, Nn);
    }

    predictor_kernel<<<gEb, 256, PRED_SMEM>>>(
        ppsrc, ppdst, pperm, px, pep,
        p1w, p1b, p1g, p1bt, p2w, p2b, p2g, p2bt, p3w, p3b, outp, E);
}

// round 17
// speedup vs baseline: 1.0771x; 1.0771x over previous
#include <cuda_runtime.h>
#include <math.h>

#define HID 96
#define HC  576
#define NH  6

typedef unsigned long long ull;

__device__ __forceinline__ unsigned f2tf32(float f) {
    unsigned r;
    asm("cvt.rna.tf32.f32 %0, %1;" : "=r"(r) : "f"(f));
    return r;
}
__device__ __forceinline__ ull pack_tf32(float a, float b) {
    unsigned lo = f2tf32(a), hi = f2tf32(b);
    ull r;
    asm("mov.b64 %0, {%1, %2};" : "=l"(r) : "r"(lo), "r"(hi));
    return r;
}
__device__ __forceinline__ void mma_tf32(float c[4],
    unsigned a0, unsigned a1, unsigned a2, unsigned a3,
    unsigned b0, unsigned b1)
{
    asm("mma.sync.aligned.m16n8k8.row.col.f32.tf32.tf32.f32 "
        "{%0,%1,%2,%3},{%4,%5,%6,%7},{%8,%9},{%0,%1,%2,%3};"
        : "+f"(c[0]), "+f"(c[1]), "+f"(c[2]), "+f"(c[3])
        : "r"(a0), "r"(a1), "r"(a2), "r"(a3), "r"(b0), "r"(b1));
}
__device__ __forceinline__ void red_add_v4(float* p, float4 v) {
    asm volatile("red.global.add.v4.f32 [%0], {%1, %2, %3, %4};"
                 :: "l"(p), "f"(v.x), "f"(v.y), "f"(v.z), "f"(v.w) : "memory");
}

// ---------------- scratch ----------------
__device__ float    g_x[20000 * HID];
__device__ float    g_eperm[200000 * HID];
__device__ float    g_xl[20000 * HC];
__device__ float    g_xr[20000 * HC];
__device__ float    g_logits[200000 * NH];
__device__ float    g_den[20000 * NH];
__device__ float    g_hmean[20000 * HID];
__device__ int      g_cnt[20000];
__device__ int      g_cur[20000];
__device__ int      g_basep[20000];
__device__ int      g_perm[200000];
__device__ int      g_psrc[200000];
__device__ int      g_pdst[200000];

__device__ __forceinline__ float warpsum32(float v) {
#pragma unroll
    for (int m = 16; m; m >>= 1) v += __shfl_xor_sync(0xffffffffu, v, m);
    return v;
}

// ---------------- sort-by-dst kernels ----------------
__global__ void hist_kernel(const int* __restrict__ dst, int* __restrict__ cnt, int E) {
    int e = blockIdx.x * blockDim.x + threadIdx.x;
    if (e < E) atomicAdd(&cnt[dst[e]], 1);
}
__global__ void scan_kernel(const int* __restrict__ cnt, int* __restrict__ base, int Nn) {
    __shared__ int wsum[32];
    int t = threadIdx.x;
    int lane = t & 31, w = t >> 5;
    int start = t * 20;
    int s = 0;
    int loc[20];
#pragma unroll
    for (int i = 0; i < 20; i++) {
        int idx = start + i;
        int v = (idx < Nn) ? cnt[idx] : 0;
        loc[i] = v; s += v;
    }
    int inc = s;
#pragma unroll
    for (int off = 1; off < 32; off <<= 1) {
        int v = __shfl_up_sync(0xffffffffu, inc, off);
        if (lane >= off) inc += v;
    }
    if (lane == 31) wsum[w] = inc;
    __syncthreads();
    if (w == 0) {
        int v = (lane < 32) ? wsum[lane] : 0;
        int wi = v;
#pragma unroll
        for (int off = 1; off < 32; off <<= 1) {
            int u = __shfl_up_sync(0xffffffffu, wi, off);
            if (lane >= off) wi += u;
        }
        wsum[lane] = wi - v;
    }
    __syncthreads();
    int run = wsum[w] + inc - s;
#pragma unroll
    for (int i = 0; i < 20; i++) {
        int idx = start + i;
        if (idx < Nn) { base[idx] = run; run += loc[i]; }
    }
}
__global__ void scatter_kernel(const int* __restrict__ src, const int* __restrict__ dst,
                               const int* __restrict__ base, int* __restrict__ cur,
                               int* __restrict__ perm, int* __restrict__ psrc,
                               int* __restrict__ pdst, int E)
{
    int e = blockIdx.x * blockDim.x + threadIdx.x;
    if (e >= E) return;
    int d = dst[e];
    int pos = base[d] + atomicAdd(&cur[d], 1);
    perm[pos] = e;
    psrc[pos] = src[e];
    pdst[pos] = d;
}

// ---------------- encoder (optional row-gather via perm) ----------------
__global__ void encoder_kernel(const float* __restrict__ in, int Fin,
                               const float* __restrict__ W, const float* __restrict__ b,
                               const float* __restrict__ g, const float* __restrict__ beta,
                               float* __restrict__ out, int M,
                               const int* __restrict__ perm)
{
    int w    = (blockIdx.x * blockDim.x + threadIdx.x) >> 5;
    int lane = threadIdx.x & 31;
    if (w >= M) return;
    int row = perm ? perm[w] : w;
    float xin[4];
#pragma unroll
    for (int k = 0; k < 4; k++) xin[k] = (k < Fin) ? in[(size_t)row * Fin + k] : 0.f;
    float v[3];
#pragma unroll
    for (int j = 0; j < 3; j++) {
        int c = lane + 32 * j;
        float acc = b[c];
        for (int k = 0; k < Fin; k++) acc = fmaf(xin[k], W[k * HID + c], acc);
        v[j] = acc;
    }
    float mu = warpsum32(v[0] + v[1] + v[2]) * (1.f / 96.f);
    float q = 0.f;
#pragma unroll
    for (int j = 0; j < 3; j++) { float d = v[j] - mu; q = fmaf(d, d, q); }
    float rstd = rsqrtf(warpsum32(q) * (1.f / 96.f) + 1e-5f);
#pragma unroll
    for (int j = 0; j < 3; j++) {
        int c = lane + 32 * j;
        float y = (v[j] - mu) * rstd * g[c] + beta[c];
        out[(size_t)w * HID + c] = fmaxf(y, 0.f);
    }
}

// ---------------- dual node tf32 GEMM: xl & xr from one A staging ----------
#define AU_ULL (12 * 512)
#define BU_ULL (12 * 384)
#define TFD_SMEM ((AU_ULL + 2 * BU_ULL) * 8)

__global__ __launch_bounds__(384) void tf32_dual_gemm_kernel(
    const float* __restrict__ Ag,
    const float* __restrict__ Bl, const float* __restrict__ Br,
    const float* __restrict__ bl, const float* __restrict__ br,
    float* __restrict__ Cl, float* __restrict__ Cr, int M)
{
    extern __shared__ ull sh64[];
    ull* Au  = sh64;
    ull* BuL = sh64 + AU_ULL;
    ull* BuR = BuL + BU_ULL;

    int tid = threadIdx.x;
    int m0 = blockIdx.x * 128, n0 = blockIdx.y * 96;

    {
        int row = tid & 127;
        int kg  = tid >> 7;
        int m = m0 + row;
        const float* arow = Ag + (size_t)m * 96;
#pragma unroll
        for (int i = 0; i < 4; i++) {
            int ks = kg * 4 + i;
            float4 lo = make_float4(0.f, 0.f, 0.f, 0.f);
            float4 hi = make_float4(0.f, 0.f, 0.f, 0.f);
            if (m < M) {
                lo = *(const float4*)(arow + ks * 8);
                hi = *(const float4*)(arow + ks * 8 + 4);
            }
            ull* dstp = Au + ks * 512 + row * 4;
            *(ulonglong2*)(dstp)     = make_ulonglong2(pack_tf32(lo.x, hi.x), pack_tf32(lo.y, hi.y));
            *(ulonglong2*)(dstp + 2) = make_ulonglong2(pack_tf32(lo.z, hi.z), pack_tf32(lo.w, hi.w));
        }
    }
    for (int t = tid; t < 2304; t += 384) {
        int side = t >= 1152;
        int tt = t - side * 1152;
        int ks  = tt / 96;
        int rem = tt - ks * 96;
        int q = rem >> 2, r = rem & 3;
        const float* Bg = side ? Br : Bl;
        const float* b0 = Bg + (size_t)(ks * 8 + r) * HC + n0 + q * 4;
        float4 lo = *(const float4*)b0;
        float4 hi = *(const float4*)(b0 + 4 * HC);
        ull* dstb = (side ? BuR : BuL) + ks * 384 + q * 16 + r;
        dstb[0]  = pack_tf32(lo.x, hi.x);
        dstb[4]  = pack_tf32(lo.y, hi.y);
        dstb[8]  = pack_tf32(lo.z, hi.z);
        dstb[12] = pack_tf32(lo.w, hi.w);
    }
    __syncthreads();

    int wid = tid >> 5, lane = tid & 31;
    int wm = wid & 3, wn = wid >> 2;
    int g = lane >> 2, tig = lane & 3;
    int rowb = wm * 32, colb = wn * 32;

#pragma unroll
    for (int side = 0; side < 2; side++) {
        const ull* Bu = side ? BuR : BuL;
        const float* bias = side ? br : bl;
        float* C = side ? Cr : Cl;

        float acc[2][4][4];
#pragma unroll
        for (int mt = 0; mt < 2; mt++)
#pragma unroll
            for (int nt = 0; nt < 4; nt++)
#pragma unroll
                for (int q = 0; q < 4; q++) acc[mt][nt][q] = 0.f;

#pragma unroll
        for (int ks = 0; ks < 12; ks++) {
            const ull* Ak = Au + ks * 512;
            const ull* Bk = Bu + ks * 384;
            uint2 pa[2][2];
#pragma unroll
            for (int mt = 0; mt < 2; mt++) {
                int rb = rowb + mt * 16 + g;
                pa[mt][0] = *(const uint2*)(Ak + rb * 4 + tig);
                pa[mt][1] = *(const uint2*)(Ak + (rb + 8) * 4 + tig);
            }
#pragma unroll
            for (int nt = 0; nt < 4; nt++) {
                int cb = colb + nt * 8 + g;
                uint2 pb = *(const uint2*)(Bk + cb * 4 + tig);
#pragma unroll
                for (int mt = 0; mt < 2; mt++)
                    mma_tf32(acc[mt][nt],
                             pa[mt][0].x, pa[mt][1].x, pa[mt][0].y, pa[mt][1].y,
                             pb.x, pb.y);
            }
        }

#pragma unroll
        for (int nt = 0; nt < 4; nt++) {
            int c = n0 + colb + nt * 8 + 2 * tig;
            float2 bq = *(const float2*)(bias + c);
#pragma unroll
            for (int mt = 0; mt < 2; mt++) {
                int r0 = m0 + rowb + mt * 16 + g;
                if (r0 < M) {
                    float2 o = make_float2(acc[mt][nt][0] + bq.x, acc[mt][nt][1] + bq.y);
                    *(float2*)(C + (size_t)r0 * HC + c) = o;
                }
                int r1 = r0 + 8;
                if (r1 < M) {
                    float2 o = make_float2(acc[mt][nt][2] + bq.x, acc[mt][nt][3] + bq.y);
                    *(float2*)(C + (size_t)r1 * HC + c) = o;
                }
            }
        }
    }
}

// ---------------- fused edge kernel: all 6 heads per block (dst-sorted) -----
#define EAU (12 * 512)
#define EBU (12 * 384)
#define EDGE_SMEM ((EAU + 2 * EBU) * 8 + 128 * 8 * 4 + 128 * 2 * 4)

__global__ __launch_bounds__(384) void edge_fused_kernel(
    const float* __restrict__ Ag, const float* __restrict__ Bg, int M,
    const int* __restrict__ src, const int* __restrict__ dst,
    const float* __restrict__ xl, const float* __restrict__ xr,
    const float* __restrict__ attw, float* __restrict__ logits,
    float* __restrict__ den)
{
    extern __shared__ ull sh64[];
    ull* Au  = sh64;
    ull* Bu0 = sh64 + EAU;
    ull* Bu1 = Bu0 + EBU;
    float* s_logit = (float*)(Bu1 + EBU);
    int*   s_src   = (int*)(s_logit + 128 * 8);
    int*   s_dst   = s_src + 128;

    int tid = threadIdx.x;
    int m0 = blockIdx.x * 128;

    for (int i = tid; i < 128 * 8; i += 384) s_logit[i] = 0.f;
    if (tid < 128) {
        int e = m0 + tid;
        int ec = (e < M) ? e : (M - 1);
        s_src[tid] = src[ec];
        s_dst[tid] = dst[ec];
    }

    {
        int row = tid & 127;
        int kg  = tid >> 7;
        int m = m0 + row;
        const float* arow = Ag + (size_t)m * 96;
#pragma unroll
        for (int i = 0; i < 4; i++) {
            int ks = kg * 4 + i;
            float4 lo = make_float4(0.f, 0.f, 0.f, 0.f);
            float4 hi = make_float4(0.f, 0.f, 0.f, 0.f);
            if (m < M) {
                lo = *(const float4*)(arow + ks * 8);
                hi = *(const float4*)(arow + ks * 8 + 4);
            }
            ull* dstp = Au + ks * 512 + row * 4;
            *(ulonglong2*)(dstp)     = make_ulonglong2(pack_tf32(lo.x, hi.x), pack_tf32(lo.y, hi.y));
            *(ulonglong2*)(dstp + 2) = make_ulonglong2(pack_tf32(lo.z, hi.z), pack_tf32(lo.w, hi.w));
        }
    }
    for (int t = tid; t < 1152; t += 384) {
        int ks  = t / 96;
        int rem = t - ks * 96;
        int q = rem >> 2, r = rem & 3;
        const float* b0 = Bg + (size_t)(ks * 8 + r) * HC + q * 4;
        float4 lo = *(const float4*)b0;
        float4 hi = *(const float4*)(b0 + 4 * HC);
        ull* dstb = Bu0 + ks * 384 + q * 16 + r;
        dstb[0]  = pack_tf32(lo.x, hi.x);
        dstb[4]  = pack_tf32(lo.y, hi.y);
        dstb[8]  = pack_tf32(lo.z, hi.z);
        dstb[12] = pack_tf32(lo.w, hi.w);
    }
    __syncthreads();

    int wid = tid >> 5, lane = tid & 31;
    int wm = wid & 3, wn = wid >> 2;
    int g = lane >> 2, tig = lane & 3;
    int rowb = wm * 32, colb = wn * 32;

    for (int h = 0; h < NH; h++) {
        ull* Bcur = (h & 1) ? Bu1 : Bu0;
        float4 plo[3], phi[3];
        if (h < 5) {
#pragma unroll
            for (int it = 0; it < 3; it++) {
                int t = tid + 384 * it;
                int ks  = t / 96;
                int rem = t - ks * 96;
                int q = rem >> 2, r = rem & 3;
                const float* b0 = Bg + (size_t)(ks * 8 + r) * HC + (h + 1) * 96 + q * 4;
                plo[it] = *(const float4*)b0;
                phi[it] = *(const float4*)(b0 + 4 * HC);
            }
        }

        float acc[2][4][4];
#pragma unroll
        for (int mt = 0; mt < 2; mt++)
#pragma unroll
            for (int nt = 0; nt < 4; nt++)
#pragma unroll
                for (int q = 0; q < 4; q++) acc[mt][nt][q] = 0.f;

#pragma unroll
        for (int ks = 0; ks < 12; ks++) {
            const ull* Ak = Au + ks * 512;
            const ull* Bk = Bcur + ks * 384;
            uint2 pa[2][2];
#pragma unroll
            for (int mt = 0; mt < 2; mt++) {
                int rb = rowb + mt * 16 + g;
                pa[mt][0] = *(const uint2*)(Ak + rb * 4 + tig);
                pa[mt][1] = *(const uint2*)(Ak + (rb + 8) * 4 + tig);
            }
#pragma unroll
            for (int nt = 0; nt < 4; nt++) {
                int cb = colb + nt * 8 + g;
                uint2 pb = *(const uint2*)(Bk + cb * 4 + tig);
#pragma unroll
                for (int mt = 0; mt < 2; mt++)
                    mma_tf32(acc[mt][nt],
                             pa[mt][0].x, pa[mt][1].x, pa[mt][0].y, pa[mt][1].y,
                             pb.x, pb.y);
            }
        }

#pragma unroll
        for (int mt = 0; mt < 2; mt++) {
#pragma unroll
            for (int half = 0; half < 2; half++) {
                int ml = rowb + mt * 16 + half * 8 + g;
                int m = m0 + ml;
                float partial = 0.f;
                if (m < M) {
                    int s = s_src[ml], d = s_dst[ml];
                    const float* xls = xl + (size_t)s * HC;
                    const float* xrd = xr + (size_t)d * HC;
#pragma unroll
                    for (int nt = 0; nt < 4; nt++) {
                        int c = h * 96 + colb + nt * 8 + 2 * tig;
                        float2 xlv = *(const float2*)(xls + c);
                        float2 xrv = *(const float2*)(xrd + c);
                        float aw0 = attw[c], aw1 = attw[c + 1];
                        float a0 = acc[mt][nt][half * 2 + 0];
                        float a1 = acc[mt][nt][half * 2 + 1];
                        float t0 = a0 + xlv.x + xrv.x; t0 = (t0 > 0.f) ? t0 : 0.2f * t0;
                        float t1 = a1 + xlv.y + xrv.y; t1 = (t1 > 0.f) ? t1 : 0.2f * t1;
                        partial = fmaf(t0, aw0, fmaf(t1, aw1, partial));
                    }
                }
                partial += __shfl_down_sync(0xffffffffu, partial, 1, 4);
                partial += __shfl_down_sync(0xffffffffu, partial, 2, 4);
                if (tig == 0 && m < M)
                    atomicAdd(&s_logit[ml * 8 + h], partial);
            }
        }

        if (h < 5) {
            ull* Bnext = (h & 1) ? Bu0 : Bu1;
#pragma unroll
            for (int it = 0; it < 3; it++) {
                int t = tid + 384 * it;
                int ks  = t / 96;
                int rem = t - ks * 96;
                int q = rem >> 2, r = rem & 3;
                ull* dstb = Bnext + ks * 384 + q * 16 + r;
                dstb[0]  = pack_tf32(plo[it].x, phi[it].x);
                dstb[4]  = pack_tf32(plo[it].y, phi[it].y);
                dstb[8]  = pack_tf32(plo[it].z, phi[it].z);
                dstb[12] = pack_tf32(plo[it].w, phi[it].w);
            }
        }
        __syncthreads();
    }

    for (int t = tid; t < 128 * NH; t += 384) {
        int el = t / NH, h = t - el * NH;
        int e = m0 + el;
        if (e < M) {
            float ex = expf(s_logit[el * 8 + h]);
            logits[(size_t)e * NH + h] = ex;
            atomicAdd(&den[s_dst[el] * NH + h], ex);
        }
    }
}

// ---------------- aggregate (red.v4) ----------------
__global__ void agg_kernel(const int* __restrict__ src, const int* __restrict__ dst,
                           const float* __restrict__ ex, const float* __restrict__ den,
                           const float* __restrict__ xl, float* __restrict__ hmean, int E)
{
    int e    = (blockIdx.x * blockDim.x + threadIdx.x) >> 5;
    int lane = threadIdx.x & 31;
    if (e >= E) return;
    int s = src[e], d = dst[e];
    float a = 0.f;
    if (lane < NH) a = ex[e * NH + lane] / (den[d * NH + lane] + 1e-16f);
    float alpha[NH];
#pragma unroll
    for (int h = 0; h < NH; h++) alpha[h] = __shfl_sync(0xffffffffu, a, h) * (1.f / 6.f);
    if (lane < 24) {
        const float* xls = xl + (size_t)s * HC + lane * 4;
        float4 v = make_float4(0.f, 0.f, 0.f, 0.f);
#pragma unroll
        for (int h = 0; h < NH; h++) {
            float4 xv = *(const float4*)(xls + h * 96);
            v.x = fmaf(alpha[h], xv.x, v.x);
            v.y = fmaf(alpha[h], xv.y, v.y);
            v.z = fmaf(alpha[h], xv.z, v.z);
            v.w = fmaf(alpha[h], xv.w, v.w);
        }
        red_add_v4(hmean + (size_t)d * HID + lane * 4, v);
    }
}

// ---------------- node update ----------------
__global__ void nodeupd_kernel(const float* __restrict__ cb, const float* __restrict__ g,
                               const float* __restrict__ bt, int doElu,
                               const float* __restrict__ hmean, float* __restrict__ x, int M)
{
    int n    = (blockIdx.x * blockDim.x + threadIdx.x) >> 5;
    int lane = threadIdx.x & 31;
    if (n >= M) return;
    float v[3];
#pragma unroll
    for (int j = 0; j < 3; j++) {
        int c = lane + 32 * j;
        float hv = hmean[(size_t)n * HID + c] + cb[c];
        if (doElu) hv = (hv > 0.f) ? hv : (expf(hv) - 1.f);
        v[j] = hv;
    }
    float mu = warpsum32(v[0] + v[1] + v[2]) * (1.f / 96.f);
    float q = 0.f;
#pragma unroll
    for (int j = 0; j < 3; j++) { float d = v[j] - mu; q = fmaf(d, d, q); }
    float rstd = rsqrtf(warpsum32(q) * (1.f / 96.f) + 1e-5f);
#pragma unroll
    for (int j = 0; j < 3; j++) {
        int c = lane + 32 * j;
        float y = (v[j] - mu) * rstd * g[c] + bt[c];
        x[(size_t)n * HID + c] += y;
    }
}

// ---------------- tf32 predictor (permuted space; scatters output) ---------
#define PAU (16 * 512)
#define PBU (12 * 512)
#define PH1 (128 * 132)
#define PCN (384 + 192 + 64)
#define PRED_SMEM ((PAU + PBU) * 8 + PH1 * 4 + (PCN + 256) * 4)

__global__ __launch_bounds__(256) void predictor_kernel(
    const int* __restrict__ src, const int* __restrict__ dst,
    const int* __restrict__ perm,
    const float* __restrict__ xnode, const float* __restrict__ eemb,
    const float* __restrict__ p1w, const float* __restrict__ p1b,
    const float* __restrict__ p1g, const float* __restrict__ p1bt,
    const float* __restrict__ p2w, const float* __restrict__ p2b,
    const float* __restrict__ p2g, const float* __restrict__ p2bt,
    const float* __restrict__ p3w, const float* __restrict__ p3b,
    float* __restrict__ out, int E)
{
    extern __shared__ ull sh64[];
    ull*   Au   = sh64;
    ull*   Bu   = sh64 + PAU;
    float* s_h1 = (float*)(Bu + PBU);
    float* s_c1 = s_h1 + PH1;
    float* s_c2 = s_c1 + 384;
    float* s_p3 = s_c2 + 192;
    int*   s_ed = (int*)(s_p3 + 64);

    int tid = threadIdx.x;
    int m0 = blockIdx.x * 128;

    if (tid < 128) {
        s_c1[tid] = p1b[tid]; s_c1[128 + tid] = p1g[tid]; s_c1[256 + tid] = p1bt[tid];
        int e = m0 + tid; int ec = (e < E) ? e : (E - 1);
        s_ed[tid] = src[ec]; s_ed[128 + tid] = dst[ec];
    }
    if (tid < 64) {
        s_c2[tid] = p2b[tid]; s_c2[64 + tid] = p2g[tid]; s_c2[128 + tid] = p2bt[tid];
        s_p3[tid] = p3w[tid];
    }
    __syncthreads();

    int wid = tid >> 5, lane = tid & 31;
    int wm = wid & 3, wn = wid >> 2;
    int g = lane >> 2, tig = lane & 3;
    int rowb = wm * 32, colb = wn * 64;

    float acc1[2][8][4];
#pragma unroll
    for (int mt = 0; mt < 2; mt++)
#pragma unroll
        for (int nt = 0; nt < 8; nt++)
#pragma unroll
            for (int q = 0; q < 4; q++) acc1[mt][nt][q] = 0.f;

    for (int c = 0; c < 3; c++) {
        {
            int row = tid & 127;
            int kg  = tid >> 7;
            const float* arow;
            if (c == 0)      arow = xnode + (size_t)s_ed[row] * HID;
            else if (c == 1) arow = xnode + (size_t)s_ed[128 + row] * HID;
            else {
                int e = m0 + row; int ec = (e < E) ? e : (E - 1);
                arow = eemb + (size_t)ec * HID;
            }
#pragma unroll
            for (int i = 0; i < 6; i++) {
                int ks = kg * 6 + i;
                float4 lo = *(const float4*)(arow + ks * 8);
                float4 hi = *(const float4*)(arow + ks * 8 + 4);
                ull* dstp = Au + ks * 512 + row * 4;
                *(ulonglong2*)(dstp)     = make_ulonglong2(pack_tf32(lo.x, hi.x), pack_tf32(lo.y, hi.y));
                *(ulonglong2*)(dstp + 2) = make_ulonglong2(pack_tf32(lo.z, hi.z), pack_tf32(lo.w, hi.w));
            }
        }
#pragma unroll
        for (int it = 0; it < 24; it++) {
            int t = tid + 256 * it;
            int ks = t >> 9, rem = t & 511;
            int col = rem >> 2, r = rem & 3;
            int k0 = c * 96 + ks * 8 + r;
            Bu[ks * 512 + col * 4 + r] =
                pack_tf32(p1w[(size_t)k0 * 128 + col], p1w[(size_t)(k0 + 4) * 128 + col]);
        }
        __syncthreads();

#pragma unroll
        for (int ks = 0; ks < 12; ks++) {
            const ull* Ak = Au + ks * 512;
            const ull* Bk = Bu + ks * 512;
            uint2 pa[2][2];
#pragma unroll
            for (int mt = 0; mt < 2; mt++) {
                int rb = rowb + mt * 16 + g;
                pa[mt][0] = *(const uint2*)(Ak + rb * 4 + tig);
                pa[mt][1] = *(const uint2*)(Ak + (rb + 8) * 4 + tig);
            }
#pragma unroll
            for (int nt = 0; nt < 8; nt++) {
                int cb = colb + nt * 8 + g;
                uint2 pb = *(const uint2*)(Bk + cb * 4 + tig);
#pragma unroll
                for (int mt = 0; mt < 2; mt++)
                    mma_tf32(acc1[mt][nt],
                             pa[mt][0].x, pa[mt][1].x, pa[mt][0].y, pa[mt][1].y,
                             pb.x, pb.y);
            }
        }
        __syncthreads();
    }

#pragma unroll
    for (int nt = 0; nt < 8; nt++) {
        int col = colb + nt * 8 + 2 * tig;
        float b0 = s_c1[col], b1 = s_c1[col + 1];
#pragma unroll
        for (int mt = 0; mt < 2; mt++) {
            int r0 = rowb + mt * 16 + g;
            s_h1[r0 * 132 + col]     = acc1[mt][nt][0] + b0;
            s_h1[r0 * 132 + col + 1] = acc1[mt][nt][1] + b1;
            int r1 = r0 + 8;
            s_h1[r1 * 132 + col]     = acc1[mt][nt][2] + b0;
            s_h1[r1 * 132 + col + 1] = acc1[mt][nt][3] + b1;
        }
    }
    __syncthreads();

    for (int rr = 0; rr < 16; rr++) {
        int row = wid * 16 + rr;
        float4 v = ((float4*)(s_h1 + row * 132))[lane];
        float mu = warpsum32(v.x + v.y + v.z + v.w) * (1.f / 128.f);
        float q = 0.f, d;
        d = v.x - mu; q = fmaf(d, d, q);
        d = v.y - mu; q = fmaf(d, d, q);
        d = v.z - mu; q = fmaf(d, d, q);
        d = v.w - mu; q = fmaf(d, d, q);
        float r = rsqrtf(warpsum32(q) * (1.f / 128.f) + 1e-5f);
        int c0 = lane * 4;
        float4 gm = *(float4*)(s_c1 + 128 + c0);
        float4 bt = *(float4*)(s_c1 + 256 + c0);
        v.x = fmaxf((v.x - mu) * r * gm.x + bt.x, 0.f);
        v.y = fmaxf((v.y - mu) * r * gm.y + bt.y, 0.f);
        v.z = fmaxf((v.z - mu) * r * gm.z + bt.z, 0.f);
        v.w = fmaxf((v.w - mu) * r * gm.w + bt.w, 0.f);
        ((float4*)(s_h1 + row * 132))[lane] = v;
    }
    __syncthreads();

    {
        int row = tid & 127;
        int kg  = tid >> 7;
        const float* hrow = s_h1 + row * 132;
#pragma unroll
        for (int i = 0; i < 8; i++) {
            int ks = kg * 8 + i;
            float4 lo = *(const float4*)(hrow + ks * 8);
            float4 hi = *(const float4*)(hrow + ks * 8 + 4);
            ull* dstp = Au + ks * 512 + row * 4;
            *(ulonglong2*)(dstp)     = make_ulonglong2(pack_tf32(lo.x, hi.x), pack_tf32(lo.y, hi.y));
            *(ulonglong2*)(dstp + 2) = make_ulonglong2(pack_tf32(lo.z, hi.z), pack_tf32(lo.w, hi.w));
        }
    }
#pragma unroll
    for (int it = 0; it < 16; it++) {
        int t = tid + 256 * it;
        int ks = t >> 8, rem = t & 255;
        int col = rem >> 2, r = rem & 3;
        int k0 = ks * 8 + r;
        Bu[ks * 256 + col * 4 + r] =
            pack_tf32(p2w[(size_t)k0 * 64 + col], p2w[(size_t)(k0 + 4) * 64 + col]);
    }
    __syncthreads();

    int colb2 = wn * 32;
    float acc2[2][4][4];
#pragma unroll
    for (int mt = 0; mt < 2; mt++)
#pragma unroll
        for (int nt = 0; nt < 4; nt++)
#pragma unroll
            for (int q = 0; q < 4; q++) acc2[mt][nt][q] = 0.f;

#pragma unroll
    for (int ks = 0; ks < 16; ks++) {
        const ull* Ak = Au + ks * 512;
        const ull* Bk = Bu + ks * 256;
        uint2 pa[2][2];
#pragma unroll
        for (int mt = 0; mt < 2; mt++) {
            int rb = rowb + mt * 16 + g;
            pa[mt][0] = *(const uint2*)(Ak + rb * 4 + tig);
            pa[mt][1] = *(const uint2*)(Ak + (rb + 8) * 4 + tig);
        }
#pragma unroll
        for (int nt = 0; nt < 4; nt++) {
            int cb = colb2 + nt * 8 + g;
            uint2 pb = *(const uint2*)(Bk + cb * 4 + tig);
#pragma unroll
            for (int mt = 0; mt < 2; mt++)
                mma_tf32(acc2[mt][nt],
                         pa[mt][0].x, pa[mt][1].x, pa[mt][0].y, pa[mt][1].y,
                         pb.x, pb.y);
        }
    }
    __syncthreads();

#pragma unroll
    for (int nt = 0; nt < 4; nt++) {
        int col = colb2 + nt * 8 + 2 * tig;
        float b0 = s_c2[col], b1 = s_c2[col + 1];
#pragma unroll
        for (int mt = 0; mt < 2; mt++) {
            int r0 = rowb + mt * 16 + g;
            s_h1[r0 * 68 + col]     = acc2[mt][nt][0] + b0;
            s_h1[r0 * 68 + col + 1] = acc2[mt][nt][1] + b1;
            int r1 = r0 + 8;
            s_h1[r1 * 68 + col]     = acc2[mt][nt][2] + b0;
            s_h1[r1 * 68 + col + 1] = acc2[mt][nt][3] + b1;
        }
    }
    __syncthreads();

    float pb = p3b[0];
    for (int rr = 0; rr < 16; rr++) {
        int row = wid * 16 + rr;
        float2 v = ((float2*)(s_h1 + row * 68))[lane];
        float mu = warpsum32(v.x + v.y) * (1.f / 64.f);
        float q = 0.f, d;
        d = v.x - mu; q = fmaf(d, d, q);
        d = v.y - mu; q = fmaf(d, d, q);
        float r = rsqrtf(warpsum32(q) * (1.f / 64.f) + 1e-5f);
        int c0 = lane * 2;
        float gm0 = s_c2[64 + c0], gm1 = s_c2[64 + c0 + 1];
        float bt0 = s_c2[128 + c0], bt1 = s_c2[128 + c0 + 1];
        float v0 = fmaxf((v.x - mu) * r * gm0 + bt0, 0.f);
        float v1 = fmaxf((v.y - mu) * r * gm1 + bt1, 0.f);
        float o = warpsum32(v0 * s_p3[c0] + v1 * s_p3[c0 + 1]);
        if (lane == 0) {
            int e = m0 + row;
            if (e < E) out[perm[e]] = o + pb;
        }
    }
}

// ---------------- launch ----------------
extern "C" void kernel_launch(void* const* d_in, const int* in_sizes, int n_in,
                              void* d_out, int out_size)
{
    const float* x         = (const float*)d_in[0];
    const float* edge_attr = (const float*)d_in[1];
    const int*   edge_idx  = (const int*)d_in[2];
    const float* ne_w = (const float*)d_in[3];
    const float* ne_b = (const float*)d_in[4];
    const float* ne_g = (const float*)d_in[5];
    const float* ne_bt = (const float*)d_in[6];
    const float* ee_w = (const float*)d_in[7];
    const float* ee_b = (const float*)d_in[8];
    const float* ee_g = (const float*)d_in[9];
    const float* ee_bt = (const float*)d_in[10];
    const float* Wl = (const float*)d_in[11];
    const float* bl = (const float*)d_in[12];
    const float* Wr = (const float*)d_in[13];
    const float* br = (const float*)d_in[14];
    const float* We = (const float*)d_in[15];
    const float* attw = (const float*)d_in[16];
    const float* cbias = (const float*)d_in[17];
    const float* lng = (const float*)d_in[18];
    const float* lnb = (const float*)d_in[19];
    const float* p1w = (const float*)d_in[20];
    const float* p1b = (const float*)d_in[21];
    const float* p1g = (const float*)d_in[22];
    const float* p1bt = (const float*)d_in[23];
    const float* p2w = (const float*)d_in[24];
    const float* p2b = (const float*)d_in[25];
    const float* p2g = (const float*)d_in[26];
    const float* p2bt = (const float*)d_in[27];
    const float* p3w = (const float*)d_in[28];
    const float* p3b = (const float*)d_in[29];

    int Nn = in_sizes[0] / 4;
    int E  = in_sizes[1] / 3;
    const int* srcp = edge_idx;
    const int* dstp = edge_idx + E;
    float* outp = (float*)d_out;

    void *px_, *pep_, *pxl_, *pxr_, *plog_, *pden_, *phm_;
    void *pcnt_, *pcur_, *pbase_, *pperm_, *ppsrc_, *ppdst_;
    cudaGetSymbolAddress(&px_, g_x);
    cudaGetSymbolAddress(&pep_, g_eperm);
    cudaGetSymbolAddress(&pxl_, g_xl);
    cudaGetSymbolAddress(&pxr_, g_xr);
    cudaGetSymbolAddress(&plog_, g_logits);
    cudaGetSymbolAddress(&pden_, g_den);
    cudaGetSymbolAddress(&phm_, g_hmean);
    cudaGetSymbolAddress(&pcnt_, g_cnt);
    cudaGetSymbolAddress(&pcur_, g_cur);
    cudaGetSymbolAddress(&pbase_, g_basep);
    cudaGetSymbolAddress(&pperm_, g_perm);
    cudaGetSymbolAddress(&ppsrc_, g_psrc);
    cudaGetSymbolAddress(&ppdst_, g_pdst);
    float* px = (float*)px_;   float* pep = (float*)pep_;
    float* pxl = (float*)pxl_; float* pxr = (float*)pxr_;
    float* plog = (float*)plog_;
    float* pden = (float*)pden_; float* phm = (float*)phm_;
    int* pcnt = (int*)pcnt_; int* pcur = (int*)pcur_; int* pbase = (int*)pbase_;
    int* pperm = (int*)pperm_; int* ppsrc = (int*)ppsrc_; int* ppdst = (int*)ppdst_;

    cudaFuncSetAttribute(tf32_dual_gemm_kernel,
                         cudaFuncAttributeMaxDynamicSharedMemorySize, TFD_SMEM);
    cudaFuncSetAttribute(edge_fused_kernel,
                         cudaFuncAttributeMaxDynamicSharedMemorySize, EDGE_SMEM);
    cudaFuncSetAttribute(predictor_kernel,
                         cudaFuncAttributeMaxDynamicSharedMemorySize, PRED_SMEM);

    // sort first (depends only on edge_index)
    cudaMemsetAsync(pcnt, 0, (size_t)Nn * sizeof(int), 0);
    cudaMemsetAsync(pcur, 0, (size_t)Nn * sizeof(int), 0);
    hist_kernel<<<(E + 255) / 256, 256>>>(dstp, pcnt, E);
    scan_kernel<<<1, 1024>>>(pcnt, pbase, Nn);
    scatter_kernel<<<(E + 255) / 256, 256>>>(srcp, dstp, pbase, pcur,
                                             pperm, ppsrc, ppdst, E);

    // encoders (edge encoder writes directly in permuted order)
    encoder_kernel<<<(Nn + 7) / 8, 256>>>(x, 4, ne_w, ne_b, ne_g, ne_bt, px, Nn,
                                          (const int*)0);
    encoder_kernel<<<(E + 7) / 8, 256>>>(edge_attr, 3, ee_w, ee_b, ee_g, ee_bt, pep, E,
                                         pperm);

    dim3 gNt((Nn + 127) / 128, HC / 96);
    int gEb = (E + 127) / 128;

    for (int l = 0; l < 3; l++) {
        const float* Wl_l = Wl + (size_t)l * 96 * HC;
        const float* Wr_l = Wr + (size_t)l * 96 * HC;
        const float* We_l = We + (size_t)l * 96 * HC;
        tf32_dual_gemm_kernel<<<gNt, 384, TFD_SMEM>>>(px, Wl_l, Wr_l,
                                                      bl + l * HC, br + l * HC,
                                                      pxl, pxr, Nn);

        cudaMemsetAsync(pden, 0, (size_t)Nn * NH * sizeof(float), 0);
        cudaMemsetAsync(phm, 0, (size_t)Nn * HID * sizeof(float), 0);

        edge_fused_kernel<<<gEb, 384, EDGE_SMEM>>>(pep, We_l, E, ppsrc, ppdst,
                                                   pxl, pxr, attw + l * NH * 96,
                                                   plog, pden);

        agg_kernel<<<(E + 7) / 8, 256>>>(ppsrc, ppdst, plog, pden, pxl, phm, E);
        nodeupd_kernel<<<(Nn + 7) / 8, 256>>>(cbias + l * HID, lng + l * HID,
                                              lnb + l * HID, (l < 2) ? 1 : 0, phm, px, Nn);
    }

    predictor_kernel<<<gEb, 256, PRED_SMEM>>>(
        ppsrc, ppdst, pperm, px, pep,
        p1w, p1b, p1g, p1bt, p2w, p2b, p2g, p2bt, p3w, p3b, outp, E);
}